// round 2
// baseline (speedup 1.0000x reference)
#include <cuda_runtime.h>

typedef unsigned long long ull;

#define NB 512
#define NS 1024
#define NL 64
#define NC 66
#define NGROUP 256
#define LN2 0.6931471805599453f

static __device__ __forceinline__ ull fma2_(ull a, ull b, ull c) {
    ull d; asm("fma.rn.f32x2 %0, %1, %2, %3;" : "=l"(d) : "l"(a), "l"(b), "l"(c)); return d;
}
static __device__ __forceinline__ ull add2_(ull a, ull b) {
    ull d; asm("add.rn.f32x2 %0, %1, %2;" : "=l"(d) : "l"(a), "l"(b)); return d;
}
static __device__ __forceinline__ ull pack2_(float lo, float hi) {
    ull d; asm("mov.b64 %0, {%1, %2};" : "=l"(d) : "f"(lo), "f"(hi)); return d;
}
static __device__ __forceinline__ float2 unpack2_(ull v) {
    float lo, hi; asm("mov.b64 {%0, %1}, %2;" : "=f"(lo), "=f"(hi) : "l"(v)); return make_float2(lo, hi);
}

__global__ void zero_out_kernel(float* out) { out[0] = 0.0f; }

__global__ void __launch_bounds__(64)
crf_fwd_kernel(const float* __restrict__ pred,
               const int*   __restrict__ ref,
               const int*   __restrict__ seq_len,
               const float* __restrict__ trans,
               float*       __restrict__ out)
{
    __shared__ __align__(16) float bufA[2][64];
    __shared__ __align__(16) float bufB[2][64];
    __shared__ float red[2][4];

    const int j = threadIdx.x;                 // state 0..63
    const int g = blockIdx.x;                  // group 0..255
    const int ba = g, bb = g + NGROUP;         // the two batches of this group
    const int La = seq_len[ba];
    const int Lb = seq_len[bb];
    const int Lmax = max(La, Lb);

    // packed E columns: e2[k] = (exp(T[2k][j]), exp(T[2k+1][j]))
    ull e2[32];
#pragma unroll
    for (int k = 0; k < 32; ++k)
        e2[k] = pack2_(__expf(trans[(2 * k) * NC + j]), __expf(trans[(2 * k + 1) * NC + j]));
    const float Te = __expf(trans[j * NC + 65]);
    const float Ts = trans[64 * NC + j];

    const float* pA = pred + (size_t)ba * NS * NL;
    const float* pB = pred + (size_t)bb * NS * NL;

    // init q1 = exp(pred0 + Ts)
    float qA = __expf(pA[j] + Ts);
    float qB = __expf(pB[j] + Ts);
    bufA[0][j] = qA;
    bufB[0][j] = qB;

    // capture init (covers L==1)
    float vA = qA * Te, vB = qB * Te;
    int   eAcap = 0,    eBcap = 0;
    int   esA = 0,      esB = 0;

    // pred row pipeline: at loop top of step t: w = exp(row[t-1]-4), r1=row[t], r2=row[t+1], r3=row[t+2]
    const int lA = La - 1, lB = Lb - 1;
    float wA = __expf(pA[(size_t)min(1, lA) * NL + j] - 4.0f);
    float wB = __expf(pB[(size_t)min(1, lB) * NL + j] - 4.0f);
    float rA1 = pA[(size_t)min(2, lA) * NL + j];
    float rB1 = pB[(size_t)min(2, lB) * NL + j];
    float rA2 = pA[(size_t)min(3, lA) * NL + j];
    float rB2 = pB[(size_t)min(3, lB) * NL + j];
    float rA3 = pA[(size_t)min(4, lA) * NL + j];
    float rB3 = pB[(size_t)min(4, lB) * NL + j];

    __syncthreads();

    for (int t = 2; t <= Lmax; ++t) {
        const int rd = t & 1;
        const int wr = rd ^ 1;
        const ulonglong2* ra = (const ulonglong2*)bufA[rd];
        const ulonglong2* rb = (const ulonglong2*)bufB[rd];

        // interleaved dual matvec: d_j = sum_i q[i] * E[i][j]
        ull a0 = 0, a1 = 0, a2 = 0, a3 = 0;
        ull b0 = 0, b1 = 0, b2 = 0, b3 = 0;
#pragma unroll
        for (int k = 0; k < 8; ++k) {
            ulonglong2 va0 = ra[2 * k];
            ulonglong2 vb0 = rb[2 * k];
            ulonglong2 va1 = ra[2 * k + 1];
            ulonglong2 vb1 = rb[2 * k + 1];
            a0 = fma2_(va0.x, e2[4 * k + 0], a0);
            b0 = fma2_(vb0.x, e2[4 * k + 0], b0);
            a1 = fma2_(va0.y, e2[4 * k + 1], a1);
            b1 = fma2_(vb0.y, e2[4 * k + 1], b1);
            a2 = fma2_(va1.x, e2[4 * k + 2], a2);
            b2 = fma2_(vb1.x, e2[4 * k + 2], b2);
            a3 = fma2_(va1.y, e2[4 * k + 3], a3);
            b3 = fma2_(vb1.y, e2[4 * k + 3], b3);
        }
        float2 fa = unpack2_(add2_(add2_(a0, a1), add2_(a2, a3)));
        float2 fb = unpack2_(add2_(add2_(b0, b1), add2_(b2, b3)));
        float qnA = (fa.x + fa.y) * wA;
        float qnB = (fb.x + fb.y) * wB;

        // O(1) renorm every 8 steps: uniform reference = q_{t-1}[0] (broadcast LDS)
        if ((t & 7) == 0) {
            float mA = bufA[rd][0];
            float mB = bufB[rd][0];
            int eA = (((__float_as_int(mA) >> 23) & 0xFF) - 127);
            int eB = (((__float_as_int(mB) >> 23) & 0xFF) - 127);
            eA = max(-80, min(80, eA));
            eB = max(-80, min(80, eB));
            qnA *= __int_as_float((unsigned)(127 - eA) << 23);
            qnB *= __int_as_float((unsigned)(127 - eB) << 23);
            esA += eA;
            esB += eB;
        }

        // capture forward terminal at each chain's own length
        if (t == La) { vA = qnA * Te; eAcap = esA; }
        if (t == Lb) { vB = qnB * Te; eBcap = esB; }

        bufA[wr][j] = qnA;
        bufB[wr][j] = qnB;

        // off-critical-path: next weights + pred pipeline rotate + prefetch
        wA = __expf(rA1 - 4.0f);
        wB = __expf(rB1 - 4.0f);
        rA1 = rA2; rA2 = rA3;
        rB1 = rB2; rB2 = rB3;
        rA3 = pA[(size_t)min(t + 3, lA) * NL + j];
        rB3 = pB[(size_t)min(t + 3, lB) * NL + j];
        asm volatile("prefetch.global.L2 [%0];" :: "l"(pA + (size_t)min(t + 8, lA) * NL + j));
        asm volatile("prefetch.global.L2 [%0];" :: "l"(pB + (size_t)min(t + 8, lB) * NL + j));

        __syncthreads();
    }

    // ---- real path scores (parallel gather) ----
    float rsA = 0.0f, rsB = 0.0f;
    const int* refA = ref + (size_t)ba * NS;
    const int* refB = ref + (size_t)bb * NS;
    for (int t = j; t < La; t += 64) {
        int r = refA[t];
        int p = (t == 0) ? 64 : refA[t - 1];
        rsA += pA[(size_t)t * NL + r] + trans[p * NC + r];
    }
    for (int t = j; t < Lb; t += 64) {
        int r = refB[t];
        int p = (t == 0) ? 64 : refB[t - 1];
        rsB += pB[(size_t)t * NL + r] + trans[p * NC + r];
    }
    if (j == 0) {
        rsA += trans[refA[La - 1] * NC + 65];
        rsB += trans[refB[Lb - 1] * NC + 65];
    }

    // ---- reduce vA, vB, rsA, rsB over the 64 threads ----
#pragma unroll
    for (int o = 16; o; o >>= 1) {
        vA  += __shfl_xor_sync(0xFFFFFFFFu, vA, o);
        vB  += __shfl_xor_sync(0xFFFFFFFFu, vB, o);
        rsA += __shfl_xor_sync(0xFFFFFFFFu, rsA, o);
        rsB += __shfl_xor_sync(0xFFFFFFFFu, rsB, o);
    }
    const int w = j >> 5;
    if ((j & 31) == 0) {
        red[w][0] = vA; red[w][1] = vB; red[w][2] = rsA; red[w][3] = rsB;
    }
    __syncthreads();
    if (j == 0) {
        float sA = red[0][0] + red[1][0];
        float sB = red[0][1] + red[1][1];
        float tA = red[0][2] + red[1][2];
        float tB = red[0][3] + red[1][3];
        float contrib = (4.0f * (float)(La - 1) + LN2 * (float)eAcap + __logf(sA) - tA)
                      + (4.0f * (float)(Lb - 1) + LN2 * (float)eBcap + __logf(sB) - tB);
        atomicAdd(out, contrib);
    }
}

extern "C" void kernel_launch(void* const* d_in, const int* in_sizes, int n_in,
                              void* d_out, int out_size)
{
    const float* pred  = (const float*)d_in[0];
    const int*   refp  = (const int*)d_in[1];
    const int*   seq   = (const int*)d_in[2];
    const float* trans = (const float*)d_in[3];
    float* outp = (float*)d_out;

    zero_out_kernel<<<1, 1>>>(outp);
    crf_fwd_kernel<<<NGROUP, 64>>>(pred, refp, seq, trans, outp);
}

// round 3
// speedup vs baseline: 3.2391x; 3.2391x over previous
#include <cuda_runtime.h>

typedef unsigned long long ull;

#define NB 512
#define NS 1024
#define NL 64
#define NC 66
#define LN2 0.6931471805599453f

static __device__ __forceinline__ ull fma2_(ull a, ull b, ull c) {
    ull d; asm("fma.rn.f32x2 %0, %1, %2, %3;" : "=l"(d) : "l"(a), "l"(b), "l"(c)); return d;
}
static __device__ __forceinline__ ull add2_(ull a, ull b) {
    ull d; asm("add.rn.f32x2 %0, %1, %2;" : "=l"(d) : "l"(a), "l"(b)); return d;
}
static __device__ __forceinline__ ull pack2_(float lo, float hi) {
    ull d; asm("mov.b64 %0, {%1, %2};" : "=l"(d) : "f"(lo), "f"(hi)); return d;
}
static __device__ __forceinline__ float2 unpack2_(ull v) {
    float lo, hi; asm("mov.b64 {%0, %1}, %2;" : "=f"(lo), "=f"(hi) : "l"(v)); return make_float2(lo, hi);
}

__global__ void zero_out_kernel(float* out) { out[0] = 0.0f; }

__global__ void __launch_bounds__(128, 1)
crf_fwd_kernel(const float* __restrict__ pred,
               const int*   __restrict__ ref,
               const int*   __restrict__ seq_len,
               const float* __restrict__ trans,
               float*       __restrict__ out)
{
    // per-warp q double buffer: 4 warps x 2 bufs x 64 floats
    __shared__ __align__(16) float qbuf[4][2][64];

    const int w = threadIdx.x >> 5;        // warp in CTA: 0..3 (one chain each)
    const int l = threadIdx.x & 31;        // lane
    const int b = (blockIdx.x << 2) + w;   // batch 0..511
    const int j0 = 2 * l, j1 = 2 * l + 1;  // the two states this thread owns
    const int L = seq_len[b];

    // E columns for states j0, j1 packed as f32x2 pairs over input-state pairs
    ull e0[32], e1[32];
#pragma unroll
    for (int k = 0; k < 32; ++k) {
        e0[k] = pack2_(__expf(trans[(2 * k) * NC + j0]), __expf(trans[(2 * k + 1) * NC + j0]));
        e1[k] = pack2_(__expf(trans[(2 * k) * NC + j1]), __expf(trans[(2 * k + 1) * NC + j1]));
    }
    const float Te0 = __expf(trans[j0 * NC + 65]);
    const float Te1 = __expf(trans[j1 * NC + 65]);

    const float* pb = pred + (size_t)b * NS * NL;

    // init: q1 = exp(pred[0] + T[start])
    float q0 = __expf(pb[j0] + trans[64 * NC + j0]);
    float q1 = __expf(pb[j1] + trans[64 * NC + j1]);

    float v = q0 * Te0 + q1 * Te1;   // covers L == 1
    int ecap = 0, esum = 0;

    float* buf0 = qbuf[w][0];
    float* buf1 = qbuf[w][1];
    ((float2*)buf0)[l] = make_float2(q0, q1);   // q_1 lives in buf0

    // pred row pipeline: at top of step t, (w0,w1) = exp(row[t-1] - 4)
    const int last = L - 1;
    float2 r1 = ((const float2*)(pb + (size_t)min(1, last) * NL))[l];
    float2 r2 = ((const float2*)(pb + (size_t)min(2, last) * NL))[l];
    float w0 = __expf(r1.x - 4.0f);
    float w1 = __expf(r1.y - 4.0f);
    r1 = r2;
    r2 = ((const float2*)(pb + (size_t)min(3, last) * NL))[l];

    __syncwarp(0xFFFFFFFFu);

    for (int t = 2; t <= L; ++t) {
        // q_t goes into buffer (t&1)^1; q_{t-1} is in buffer (t&1)
        const float* rp = (t & 1) ? buf1 : buf0;
        float*       wp = (t & 1) ? buf0 : buf1;
        const ulonglong2* rp2 = (const ulonglong2*)rp;

        // d_j = sum_i q_{t-1}[i] * E[i][j] for j in {j0, j1}
        ull a0 = 0, a1 = 0, c0 = 0, c1 = 0;
#pragma unroll
        for (int k = 0; k < 16; ++k) {
            ulonglong2 qv = rp2[k];                 // broadcast LDS.128 (conflict-free)
            a0 = fma2_(qv.x, e0[2 * k],     a0);
            c0 = fma2_(qv.x, e1[2 * k],     c0);
            a1 = fma2_(qv.y, e0[2 * k + 1], a1);
            c1 = fma2_(qv.y, e1[2 * k + 1], c1);
        }
        float2 fa = unpack2_(add2_(a0, a1));
        float2 fc = unpack2_(add2_(c0, c1));
        float d0 = (fa.x + fa.y) * w0;
        float d1 = (fc.x + fc.y) * w1;

        // O(1) renorm every 8 steps (exact power of 2, uniform across warp)
        if ((t & 7) == 0) {
            float m = rp[0];
            int e = ((__float_as_int(m) >> 23) & 0xFF) - 127;
            e = max(-100, min(100, e));
            float f = __int_as_float((unsigned)(127 - e) << 23);  // 2^-e
            d0 *= f; d1 *= f;
            esum += e;
        }

        if (t == L) { v = d0 * Te0 + d1 * Te1; ecap = esum; }

        ((float2*)wp)[l] = make_float2(d0, d1);

        // off-critical-path: next weight + pred pipeline rotate + prefetch
        w0 = __expf(r1.x - 4.0f);
        w1 = __expf(r1.y - 4.0f);
        r1 = r2;
        r2 = ((const float2*)(pb + (size_t)min(t + 2, last) * NL))[l];
        asm volatile("prefetch.global.L2 [%0];" :: "l"(pb + (size_t)min(t + 6, last) * NL + j0));

        __syncwarp(0xFFFFFFFFu);
    }

    // ---- real path score (lane-strided gather, off the chain) ----
    float rsum = 0.0f;
    const int* rb = ref + (size_t)b * NS;
    for (int t = l; t < L; t += 32) {
        int r = rb[t];
        int p = (t == 0) ? 64 : rb[t - 1];
        rsum += pb[(size_t)t * NL + r] + trans[p * NC + r];
    }
    if (l == 0) rsum += trans[rb[L - 1] * NC + 65];

    // ---- in-warp reduction; one atomic per chain ----
#pragma unroll
    for (int o = 16; o; o >>= 1) {
        v    += __shfl_xor_sync(0xFFFFFFFFu, v, o);
        rsum += __shfl_xor_sync(0xFFFFFFFFu, rsum, o);
    }
    if (l == 0) {
        float contrib = 4.0f * (float)(L - 1) + LN2 * (float)ecap + logf(v) - rsum;
        atomicAdd(out, contrib);
    }
}

extern "C" void kernel_launch(void* const* d_in, const int* in_sizes, int n_in,
                              void* d_out, int out_size)
{
    const float* pred  = (const float*)d_in[0];
    const int*   refp  = (const int*)d_in[1];
    const int*   seq   = (const int*)d_in[2];
    const float* trans = (const float*)d_in[3];
    float* outp = (float*)d_out;

    zero_out_kernel<<<1, 1>>>(outp);
    crf_fwd_kernel<<<NB / 4, 128>>>(pred, refp, seq, trans, outp);
}